// round 16
// baseline (speedup 1.0000x reference)
#include <cuda_runtime.h>
#include <cuda_fp16.h>
#include <cstdint>

// ---------------------------------------------------------------------------
// TeamMovementModel R16: R15 two-group pipelined HMMA LSTM + CONVOY BREAK.
// R14 profile arithmetic: tensor-active (~909 cyc/step) + MUFU (~640) ~= the
// measured step (~1570) -> the two pipes never overlap because all warps run
// [mma; epi] in identical order after each bar. Fix: odd warps run [epi; mma],
// even warps [mma; epi] -> both pipes fill simultaneously.
// fc: one CTA per batch (64x896), fw smem amortized over 22 players.
//   92 CTAs x 16 seqs, 512 threads, K=128 fp16, fp32 c-state.
// ---------------------------------------------------------------------------

#define Hh        128
#define GATES     512
#define Tt        128
#define SEQS      16
#define NCTAS     92
#define PCTAS     88
#define NPLAYER   1408
#define NBALL     64
#define THREADS   512
#define NKT       8             // K tiles of 16 (K=128)
#define BS        136           // h tile row stride in halves (conflict-free)

__device__ float g_hid[(NPLAYER + NBALL) * Hh];

__device__ __forceinline__ float tanhap(float x) {
    float y; asm("tanh.approx.f32 %0, %1;" : "=f"(y) : "f"(x)); return y;
}
__device__ __forceinline__ float sigap(float x) {
    return fmaf(0.5f, tanhap(0.5f * x), 0.5f);
}
__device__ __forceinline__ uint32_t h2pack(float a, float b) {
    __half2 h = __halves2half2(__float2half(a), __float2half(b));
    return *reinterpret_cast<uint32_t*>(&h);
}

// m16n8k16 row.col f32.f16.f16.f32, accumulate in place.
__device__ __forceinline__ void mma16816(float* d, const uint32_t* a,
                                         uint32_t b0, uint32_t b1) {
    asm volatile(
        "mma.sync.aligned.m16n8k16.row.col.f32.f16.f16.f32 "
        "{%0,%1,%2,%3}, {%4,%5,%6,%7}, {%8,%9}, {%0,%1,%2,%3};"
        : "+f"(d[0]), "+f"(d[1]), "+f"(d[2]), "+f"(d[3])
        : "r"(a[0]), "r"(a[1]), "r"(a[2]), "r"(a[3]), "r"(b0), "r"(b1));
}

// MMA phase for one 8-seq group.
#define MMA_PHASE(DG, HT, XF) do {                                             \
    _Pragma("unroll")                                                          \
    for (int e1 = 0; e1 < 2; e1++) {                                           \
        const float2 x = (XF)[e1];                                             \
        (DG)[0][e1]     = fmaf(wx1[0], x.y, fmaf(wx0[0], x.x, bsr[0]));        \
        (DG)[0][2 + e1] = fmaf(wx1[1], x.y, fmaf(wx0[1], x.x, bsr[1]));        \
        (DG)[1][e1]     = fmaf(wx1[2], x.y, fmaf(wx0[2], x.x, bsr[2]));        \
        (DG)[1][2 + e1] = fmaf(wx1[3], x.y, fmaf(wx0[3], x.x, bsr[3]));        \
    }                                                                          \
    _Pragma("unroll")                                                          \
    for (int kt = 0; kt < NKT; kt++) {                                         \
        const __half* bp = (HT) + r0 * BS + kt * 16 + c0;                      \
        const uint32_t b0 = *reinterpret_cast<const uint32_t*>(bp);            \
        const uint32_t b1 = *reinterpret_cast<const uint32_t*>(bp + 8);        \
        mma16816((DG)[0], Af[0][kt], b0, b1);                                  \
        mma16816((DG)[1], Af[1][kt], b0, b1);                                  \
    }                                                                          \
} while (0)

// Epilogue for one group.
#define EPI_PHASE(DG, CC, HT, GSEQ0, LAST) do {                                \
    _Pragma("unroll")                                                          \
    for (int e1 = 0; e1 < 2; e1++) {                                           \
        const int m = c0 + e1;                                                 \
        const float gi = sigap((DG)[0][e1]);                                   \
        const float gf = sigap((DG)[0][2 + e1]);                               \
        const float gg = tanhap((DG)[1][e1]);                                  \
        const float go = sigap((DG)[1][2 + e1]);                               \
        (CC)[e1] = gf * (CC)[e1] + gi * gg;                                    \
        const float h = go * tanhap((CC)[e1]);                                 \
        (HT)[m * BS + u] = __float2half(h);                                    \
        if (LAST)                                                              \
            g_hid[(size_t)((GSEQ0) + m) * Hh + u] = h;                         \
    }                                                                          \
} while (0)

__global__ __launch_bounds__(THREADS, 1)
void lstm_hmma_kernel(const float* __restrict__ xp, const float* __restrict__ xb,
                      const float* __restrict__ p_wih, const float* __restrict__ p_whh,
                      const float* __restrict__ p_bih, const float* __restrict__ p_bhh,
                      const float* __restrict__ b_wih, const float* __restrict__ b_whh,
                      const float* __restrict__ b_bih, const float* __restrict__ b_bhh)
{
    __shared__ float2 xs[Tt * SEQS];              // [t][s]  16 KB
    __shared__ __half hA[8 * BS];                 // group A h tile (seqs 0-7)
    __shared__ __half hB[8 * BS];                 // group B h tile (seqs 8-15)

    const int tid = threadIdx.x;
    const int w   = tid >> 5;          // 0..15 -> units [8w, 8w+8)
    const int ln  = tid & 31;
    const int cta = blockIdx.x;
    const bool is_ball = (cta >= PCTAS);
    const bool epi_first = (w & 1);    // convoy break: odd warps epi-first

    const float* wih_ = is_ball ? b_wih : p_wih;
    const float* whh_ = is_ball ? b_whh : p_whh;
    const float* bih_ = is_ball ? b_bih : p_bih;
    const float* bhh_ = is_ball ? b_bhh : p_bhh;
    const float* xsrc = is_ball ? xb : xp;
    const int s0    = is_ball ? (cta - PCTAS) * SEQS : cta * SEQS;
    const int gbase = is_ball ? NPLAYER + s0 : s0;

    // ---- zero h tiles, stage x ----
    for (int i = tid; i < 8 * BS / 2; i += THREADS) {
        reinterpret_cast<uint32_t*>(hA)[i] = 0;
        reinterpret_cast<uint32_t*>(hB)[i] = 0;
    }
    for (int i = tid; i < Tt * SEQS; i += THREADS) {
        int s = i >> 7, t = i & 127;
        xs[t * SEQS + s] = *reinterpret_cast<const float2*>(
            xsrc + (size_t)(s0 + s) * 256 + t * 2);
    }

    const int r0 = ln >> 2;            // 0..7
    const int c0 = (ln & 3) * 2;       // 0,2,4,6
    const int u  = w * 8 + r0;         // hidden unit owned by this thread

    // ---- A fragments: mt0 rows = {i(u), f(u)}, mt1 rows = {g(u), o(u)} ----
    uint32_t Af[2][NKT][4];
    #pragma unroll
    for (int mt = 0; mt < 2; mt++) {
        const float* wrA = whh_ + (size_t)((mt * 2 + 0) * Hh + u) * Hh;  // i or g
        const float* wrB = whh_ + (size_t)((mt * 2 + 1) * Hh + u) * Hh;  // f or o
        #pragma unroll
        for (int kt = 0; kt < NKT; kt++) {
            const int k = kt * 16 + c0;
            float2 aA0 = *reinterpret_cast<const float2*>(wrA + k);
            float2 aB0 = *reinterpret_cast<const float2*>(wrB + k);
            float2 aA1 = *reinterpret_cast<const float2*>(wrA + k + 8);
            float2 aB1 = *reinterpret_cast<const float2*>(wrB + k + 8);
            Af[mt][kt][0] = h2pack(aA0.x, aA0.y);
            Af[mt][kt][1] = h2pack(aB0.x, aB0.y);
            Af[mt][kt][2] = h2pack(aA1.x, aA1.y);
            Af[mt][kt][3] = h2pack(aB1.x, aB1.y);
        }
    }

    // ---- per-gate x-weights and bias for unit u (i, f, g, o) ----
    float wx0[4], wx1[4], bsr[4];
    #pragma unroll
    for (int q = 0; q < 4; q++) {
        const int g = q * Hh + u;
        wx0[q] = wih_[g * 2 + 0];
        wx1[q] = wih_[g * 2 + 1];
        bsr[q] = bih_[g] + bhh_[g];
    }

    float cA[2] = {0.f, 0.f}, cB[2] = {0.f, 0.f};
    float DA[2][4], DB[2][4];
    float2 xfA[2], xfB[2];

    __syncthreads();

    xfA[0] = xs[0 * SEQS + c0];
    xfA[1] = xs[0 * SEQS + c0 + 1];

    // ---- pipeline prologue: t = 0 ----
    MMA_PHASE(DA, hA, xfA);
    xfB[0] = xs[0 * SEQS + 8 + c0];
    xfB[1] = xs[0 * SEQS + 8 + c0 + 1];
    __syncthreads();
    if (epi_first) {
        EPI_PHASE(DA, cA, hA, gbase, false);
        MMA_PHASE(DB, hB, xfB);
    } else {
        MMA_PHASE(DB, hB, xfB);
        EPI_PHASE(DA, cA, hA, gbase, false);
    }
    xfA[0] = xs[1 * SEQS + c0];
    xfA[1] = xs[1 * SEQS + c0 + 1];
    __syncthreads();

    // ---- main pipeline: t = 1..127 ----
    #pragma unroll 1
    for (int t = 1; t < Tt; t++) {
        // phase 1: mmaA(t) || epiB(t-1), staggered per warp parity
        if (epi_first) {
            EPI_PHASE(DB, cB, hB, gbase + 8, false);
            MMA_PHASE(DA, hA, xfA);
        } else {
            MMA_PHASE(DA, hA, xfA);
            EPI_PHASE(DB, cB, hB, gbase + 8, false);
        }
        xfB[0] = xs[t * SEQS + 8 + c0];
        xfB[1] = xs[t * SEQS + 8 + c0 + 1];
        __syncthreads();
        // phase 2: mmaB(t) || epiA(t), staggered per warp parity
        if (epi_first) {
            EPI_PHASE(DA, cA, hA, gbase, t == Tt - 1);
            MMA_PHASE(DB, hB, xfB);
        } else {
            MMA_PHASE(DB, hB, xfB);
            EPI_PHASE(DA, cA, hA, gbase, t == Tt - 1);
        }
        if (t + 1 < Tt) {
            xfA[0] = xs[(t + 1) * SEQS + c0];
            xfA[1] = xs[(t + 1) * SEQS + c0 + 1];
        }
        __syncthreads();
    }

    // ---- pipeline epilogue: epiB(127) ----
    EPI_PHASE(DB, cB, hB, gbase + 8, true);
}

// FC: one CTA per batch b (64 CTAs x 896 threads); fw smem shared by 22 players.
#define FC_THREADS 896
__global__ __launch_bounds__(FC_THREADS)
void fc_kernel(const float* __restrict__ fc_w,
               const float* __restrict__ fc_b,
               float* __restrict__ out)
{
    __shared__ float fw[40 * 258];     // [40][258] padded
    __shared__ float ph[22 * 128];
    __shared__ float ball[128];

    const int b   = blockIdx.x;
    const int tid = threadIdx.x;

    for (int idx = tid; idx < 40 * 256; idx += FC_THREADS) {
        int j = idx >> 8, k = idx & 255;
        fw[j * 258 + k] = fc_w[idx];
    }
    for (int idx = tid; idx < 22 * 128; idx += FC_THREADS) {
        int p = idx >> 7, k = idx & 127;
        ph[idx] = g_hid[(b * 22 + p) * Hh + k];
    }
    for (int idx = tid; idx < 128; idx += FC_THREADS)
        ball[idx] = g_hid[(NPLAYER + b) * Hh + idx];
    __syncthreads();

    if (tid < 880) {
        const int p = tid / 40;
        const int j = tid - p * 40;
        const float2* php  = (const float2*)(ph + p * 128);
        const float2* blp  = (const float2*)(ball);
        const float2* fwp0 = (const float2*)(fw + j * 258);
        const float2* fwp1 = (const float2*)(fw + j * 258 + 128);
        float acc = fc_b[j];
        #pragma unroll 8
        for (int k2 = 0; k2 < 64; k2++) {
            float2 hp = php[k2], hb = blp[k2];
            float2 w0 = fwp0[k2], w1 = fwp1[k2];
            acc += hp.x * w0.x + hp.y * w0.y + hb.x * w1.x + hb.y * w1.y;
        }
        out[(b * 22 + p) * 40 + j] = acc;
    }
}

extern "C" void kernel_launch(void* const* d_in, const int* in_sizes, int n_in,
                              void* d_out, int out_size)
{
    const float* xp    = (const float*)d_in[0];
    const float* xb    = (const float*)d_in[1];
    const float* p_wih = (const float*)d_in[2];
    const float* p_whh = (const float*)d_in[3];
    const float* p_bih = (const float*)d_in[4];
    const float* p_bhh = (const float*)d_in[5];
    const float* b_wih = (const float*)d_in[6];
    const float* b_whh = (const float*)d_in[7];
    const float* b_bih = (const float*)d_in[8];
    const float* b_bhh = (const float*)d_in[9];
    const float* fc_w  = (const float*)d_in[10];
    const float* fc_b  = (const float*)d_in[11];
    float* out = (float*)d_out;

    lstm_hmma_kernel<<<NCTAS, THREADS>>>(xp, xb,
                                         p_wih, p_whh, p_bih, p_bhh,
                                         b_wih, b_whh, b_bih, b_bhh);
    fc_kernel<<<64, FC_THREADS>>>(fc_w, fc_b, out);
}

// round 17
// speedup vs baseline: 1.2511x; 1.2511x over previous
#include <cuda_runtime.h>
#include <cuda_fp16.h>
#include <cstdint>

// ---------------------------------------------------------------------------
// TeamMovementModel R17: R15 two-group pipelined HMMA LSTM + INTRA-WARP
// instruction-level interleave. R15's step ~= tensor-active + MUFU time
// (pipes sum-serialized). Fix inside each warp's stream: the other group's
// epilogue MUFU ops are interleaved between the volatile MMA bursts, so
// HMMA and MUFU issue alternately and the pipes overlap.
// (R16's warp-parity stagger + 64-CTA fc reverted: measured regression.)
//   92 CTAs x 16 seqs, 512 threads, K=128 fp16, fp32 c-state.
// ---------------------------------------------------------------------------

#define Hh        128
#define GATES     512
#define Tt        128
#define SEQS      16
#define NCTAS     92
#define PCTAS     88
#define NPLAYER   1408
#define NBALL     64
#define THREADS   512
#define NKT       8             // K tiles of 16 (K=128)
#define BS        136           // h tile row stride in halves (conflict-free)

__device__ float g_hid[(NPLAYER + NBALL) * Hh];

// volatile tanh: pinned placement (the interleave IS the optimization)
__device__ __forceinline__ float tanhv(float x) {
    float y; asm volatile("tanh.approx.f32 %0, %1;" : "=f"(y) : "f"(x)); return y;
}
__device__ __forceinline__ float sigv(float x) {
    return fmaf(0.5f, tanhv(0.5f * x), 0.5f);
}
__device__ __forceinline__ uint32_t h2pack(float a, float b) {
    __half2 h = __halves2half2(__float2half(a), __float2half(b));
    return *reinterpret_cast<uint32_t*>(&h);
}

// m16n8k16 row.col f32.f16.f16.f32, accumulate in place.
__device__ __forceinline__ void mma16816(float* d, const uint32_t* a,
                                         uint32_t b0, uint32_t b1) {
    asm volatile(
        "mma.sync.aligned.m16n8k16.row.col.f32.f16.f16.f32 "
        "{%0,%1,%2,%3}, {%4,%5,%6,%7}, {%8,%9}, {%0,%1,%2,%3};"
        : "+f"(d[0]), "+f"(d[1]), "+f"(d[2]), "+f"(d[3])
        : "r"(a[0]), "r"(a[1]), "r"(a[2]), "r"(a[3]), "r"(b0), "r"(b1));
}

// one K-tile (2 MMAs) for group tile HT into DG
#define MMA_KT(DG, HT, KT) do {                                                \
    const __half* bp = (HT) + r0 * BS + (KT) * 16 + c0;                        \
    const uint32_t b0 = *reinterpret_cast<const uint32_t*>(bp);                \
    const uint32_t b1 = *reinterpret_cast<const uint32_t*>(bp + 8);            \
    mma16816((DG)[0], Af[0][KT], b0, b1);                                      \
    mma16816((DG)[1], Af[1][KT], b0, b1);                                      \
} while (0)

// D init: bias + exact fp32 x-projection
#define D_INIT(DG, XF) do {                                                    \
    _Pragma("unroll")                                                          \
    for (int e1 = 0; e1 < 2; e1++) {                                           \
        const float2 x = (XF)[e1];                                             \
        (DG)[0][e1]     = fmaf(wx1[0], x.y, fmaf(wx0[0], x.x, bsr[0]));        \
        (DG)[0][2 + e1] = fmaf(wx1[1], x.y, fmaf(wx0[1], x.x, bsr[1]));        \
        (DG)[1][e1]     = fmaf(wx1[2], x.y, fmaf(wx0[2], x.x, bsr[2]));        \
        (DG)[1][2 + e1] = fmaf(wx1[3], x.y, fmaf(wx0[3], x.x, bsr[3]));        \
    }                                                                          \
} while (0)

// Interleaved phase: MMA group X (DX <- HX, XFX) with the epilogue of group Y
// (DY -> CY, h into HY) woven between the MMA bursts.
#define PHASE_IL(DX, HX, XFX, DY, CY, HY, GSEQ0, LAST) do {                    \
    D_INIT(DX, XFX);                                                           \
    MMA_KT(DX, HX, 0); MMA_KT(DX, HX, 1);                                      \
    const float gi0 = sigv((DY)[0][0]);                                        \
    const float gf0 = sigv((DY)[0][2]);                                        \
    MMA_KT(DX, HX, 2); MMA_KT(DX, HX, 3);                                      \
    const float gg0 = tanhv((DY)[1][0]);                                       \
    const float go0 = sigv((DY)[1][2]);                                        \
    (CY)[0] = gf0 * (CY)[0] + gi0 * gg0;                                       \
    MMA_KT(DX, HX, 4); MMA_KT(DX, HX, 5);                                      \
    const float h0 = go0 * tanhv((CY)[0]);                                     \
    (HY)[c0 * BS + u] = __float2half(h0);                                      \
    if (LAST) g_hid[(size_t)((GSEQ0) + c0) * Hh + u] = h0;                     \
    const float gi1 = sigv((DY)[0][1]);                                        \
    const float gf1 = sigv((DY)[0][3]);                                        \
    MMA_KT(DX, HX, 6); MMA_KT(DX, HX, 7);                                      \
    const float gg1 = tanhv((DY)[1][1]);                                       \
    const float go1 = sigv((DY)[1][3]);                                        \
    (CY)[1] = gf1 * (CY)[1] + gi1 * gg1;                                       \
    const float h1 = go1 * tanhv((CY)[1]);                                     \
    (HY)[(c0 + 1) * BS + u] = __float2half(h1);                                \
    if (LAST) g_hid[(size_t)((GSEQ0) + c0 + 1) * Hh + u] = h1;                 \
} while (0)

// plain phases for prologue/epilogue
#define MMA_PHASE(DG, HT, XF) do {                                             \
    D_INIT(DG, XF);                                                            \
    _Pragma("unroll")                                                          \
    for (int kt = 0; kt < NKT; kt++) MMA_KT(DG, HT, kt);                       \
} while (0)

#define EPI_PHASE(DG, CC, HT, GSEQ0, LAST) do {                                \
    _Pragma("unroll")                                                          \
    for (int e1 = 0; e1 < 2; e1++) {                                           \
        const int m = c0 + e1;                                                 \
        const float gi = sigv((DG)[0][e1]);                                    \
        const float gf = sigv((DG)[0][2 + e1]);                                \
        const float gg = tanhv((DG)[1][e1]);                                   \
        const float go = sigv((DG)[1][2 + e1]);                                \
        (CC)[e1] = gf * (CC)[e1] + gi * gg;                                    \
        const float h = go * tanhv((CC)[e1]);                                  \
        (HT)[m * BS + u] = __float2half(h);                                    \
        if (LAST) g_hid[(size_t)((GSEQ0) + m) * Hh + u] = h;                   \
    }                                                                          \
} while (0)

__global__ __launch_bounds__(THREADS, 1)
void lstm_hmma_kernel(const float* __restrict__ xp, const float* __restrict__ xb,
                      const float* __restrict__ p_wih, const float* __restrict__ p_whh,
                      const float* __restrict__ p_bih, const float* __restrict__ p_bhh,
                      const float* __restrict__ b_wih, const float* __restrict__ b_whh,
                      const float* __restrict__ b_bih, const float* __restrict__ b_bhh)
{
    __shared__ float2 xs[Tt * SEQS];              // [t][s]  16 KB
    __shared__ __half hA[8 * BS];                 // group A h tile (seqs 0-7)
    __shared__ __half hB[8 * BS];                 // group B h tile (seqs 8-15)

    const int tid = threadIdx.x;
    const int w   = tid >> 5;          // 0..15 -> units [8w, 8w+8)
    const int ln  = tid & 31;
    const int cta = blockIdx.x;
    const bool is_ball = (cta >= PCTAS);

    const float* wih_ = is_ball ? b_wih : p_wih;
    const float* whh_ = is_ball ? b_whh : p_whh;
    const float* bih_ = is_ball ? b_bih : p_bih;
    const float* bhh_ = is_ball ? b_bhh : p_bhh;
    const float* xsrc = is_ball ? xb : xp;
    const int s0    = is_ball ? (cta - PCTAS) * SEQS : cta * SEQS;
    const int gbase = is_ball ? NPLAYER + s0 : s0;

    // ---- zero h tiles, stage x ----
    for (int i = tid; i < 8 * BS / 2; i += THREADS) {
        reinterpret_cast<uint32_t*>(hA)[i] = 0;
        reinterpret_cast<uint32_t*>(hB)[i] = 0;
    }
    for (int i = tid; i < Tt * SEQS; i += THREADS) {
        int s = i >> 7, t = i & 127;
        xs[t * SEQS + s] = *reinterpret_cast<const float2*>(
            xsrc + (size_t)(s0 + s) * 256 + t * 2);
    }

    const int r0 = ln >> 2;            // 0..7
    const int c0 = (ln & 3) * 2;       // 0,2,4,6
    const int u  = w * 8 + r0;         // hidden unit owned by this thread

    // ---- A fragments: mt0 rows = {i(u), f(u)}, mt1 rows = {g(u), o(u)} ----
    uint32_t Af[2][NKT][4];
    #pragma unroll
    for (int mt = 0; mt < 2; mt++) {
        const float* wrA = whh_ + (size_t)((mt * 2 + 0) * Hh + u) * Hh;  // i or g
        const float* wrB = whh_ + (size_t)((mt * 2 + 1) * Hh + u) * Hh;  // f or o
        #pragma unroll
        for (int kt = 0; kt < NKT; kt++) {
            const int k = kt * 16 + c0;
            float2 aA0 = *reinterpret_cast<const float2*>(wrA + k);
            float2 aB0 = *reinterpret_cast<const float2*>(wrB + k);
            float2 aA1 = *reinterpret_cast<const float2*>(wrA + k + 8);
            float2 aB1 = *reinterpret_cast<const float2*>(wrB + k + 8);
            Af[mt][kt][0] = h2pack(aA0.x, aA0.y);
            Af[mt][kt][1] = h2pack(aB0.x, aB0.y);
            Af[mt][kt][2] = h2pack(aA1.x, aA1.y);
            Af[mt][kt][3] = h2pack(aB1.x, aB1.y);
        }
    }

    // ---- per-gate x-weights and bias for unit u (i, f, g, o) ----
    float wx0[4], wx1[4], bsr[4];
    #pragma unroll
    for (int q = 0; q < 4; q++) {
        const int g = q * Hh + u;
        wx0[q] = wih_[g * 2 + 0];
        wx1[q] = wih_[g * 2 + 1];
        bsr[q] = bih_[g] + bhh_[g];
    }

    float cA[2] = {0.f, 0.f}, cB[2] = {0.f, 0.f};
    float DA[2][4], DB[2][4];
    float2 xfA[2], xfB[2];

    __syncthreads();

    xfA[0] = xs[0 * SEQS + c0];
    xfA[1] = xs[0 * SEQS + c0 + 1];

    // ---- pipeline prologue: t = 0 ----
    MMA_PHASE(DA, hA, xfA);
    xfB[0] = xs[0 * SEQS + 8 + c0];
    xfB[1] = xs[0 * SEQS + 8 + c0 + 1];
    __syncthreads();
    // phase: mmaB(0) interleaved with epiA(0)
    PHASE_IL(DB, hB, xfB, DA, cA, hA, gbase, false);
    xfA[0] = xs[1 * SEQS + c0];
    xfA[1] = xs[1 * SEQS + c0 + 1];
    __syncthreads();

    // ---- main pipeline: t = 1..127 ----
    #pragma unroll 1
    for (int t = 1; t < Tt; t++) {
        // phase 1: mmaA(t) || epiB(t-1), interleaved within the warp
        PHASE_IL(DA, hA, xfA, DB, cB, hB, gbase + 8, false);
        xfB[0] = xs[t * SEQS + 8 + c0];
        xfB[1] = xs[t * SEQS + 8 + c0 + 1];
        __syncthreads();
        // phase 2: mmaB(t) || epiA(t), interleaved within the warp
        PHASE_IL(DB, hB, xfB, DA, cA, hA, gbase, t == Tt - 1);
        if (t + 1 < Tt) {
            xfA[0] = xs[(t + 1) * SEQS + c0];
            xfA[1] = xs[(t + 1) * SEQS + c0 + 1];
        }
        __syncthreads();
    }

    // ---- pipeline epilogue: epiB(127) ----
    EPI_PHASE(DB, cB, hB, gbase + 8, true);
}

// FC: 128 blocks = (batch b, half of 22 players). fc_w + hidden states in smem.
#define FC_THREADS 448
__global__ __launch_bounds__(FC_THREADS)
void fc_kernel(const float* __restrict__ fc_w,
               const float* __restrict__ fc_b,
               float* __restrict__ out)
{
    __shared__ float fw[40 * 258];
    __shared__ float ph[11 * 128];
    __shared__ float ball[128];

    const int bx   = blockIdx.x;
    const int b    = bx >> 1;
    const int half = bx & 1;
    const int tid  = threadIdx.x;

    for (int idx = tid; idx < 40 * 256; idx += FC_THREADS) {
        int j = idx >> 8, k = idx & 255;
        fw[j * 258 + k] = fc_w[idx];
    }
    for (int idx = tid; idx < 11 * 128; idx += FC_THREADS) {
        int p = idx >> 7, k = idx & 127;
        ph[idx] = g_hid[(b * 22 + half * 11 + p) * Hh + k];
    }
    for (int idx = tid; idx < 128; idx += FC_THREADS)
        ball[idx] = g_hid[(NPLAYER + b) * Hh + idx];
    __syncthreads();

    if (tid < 440) {
        const int p = tid / 40;
        const int j = tid - p * 40;
        const float2* php  = (const float2*)(ph + p * 128);
        const float2* blp  = (const float2*)(ball);
        const float2* fwp0 = (const float2*)(fw + j * 258);
        const float2* fwp1 = (const float2*)(fw + j * 258 + 128);
        float acc = fc_b[j];
        #pragma unroll 8
        for (int k2 = 0; k2 < 64; k2++) {
            float2 hp = php[k2], hb = blp[k2];
            float2 w0 = fwp0[k2], w1 = fwp1[k2];
            acc += hp.x * w0.x + hp.y * w0.y + hb.x * w1.x + hb.y * w1.y;
        }
        out[(b * 22 + half * 11 + p) * 40 + j] = acc;
    }
}

extern "C" void kernel_launch(void* const* d_in, const int* in_sizes, int n_in,
                              void* d_out, int out_size)
{
    const float* xp    = (const float*)d_in[0];
    const float* xb    = (const float*)d_in[1];
    const float* p_wih = (const float*)d_in[2];
    const float* p_whh = (const float*)d_in[3];
    const float* p_bih = (const float*)d_in[4];
    const float* p_bhh = (const float*)d_in[5];
    const float* b_wih = (const float*)d_in[6];
    const float* b_whh = (const float*)d_in[7];
    const float* b_bih = (const float*)d_in[8];
    const float* b_bhh = (const float*)d_in[9];
    const float* fc_w  = (const float*)d_in[10];
    const float* fc_b  = (const float*)d_in[11];
    float* out = (float*)d_out;

    lstm_hmma_kernel<<<NCTAS, THREADS>>>(xp, xb,
                                         p_wih, p_whh, p_bih, p_bhh,
                                         b_wih, b_whh, b_bih, b_bhh);
    fc_kernel<<<128, FC_THREADS>>>(fc_w, fc_b, out);
}